// round 1
// baseline (speedup 1.0000x reference)
#include <cuda_runtime.h>

#define N_NODES 100000
#define N_EDGES 1600000
#define HID 64
#define DENSE 128
#define OUTD 10
#define N_GRAPHS 128
#define SCAN_NB 98   // ceil(100000/1024)

// ---------------- device scratch (no allocations allowed) ----------------
__device__ float g_Xa[N_NODES * HID];
__device__ float g_Xb[N_NODES * HID];
__device__ float g_H [N_NODES * HID];
__device__ float g_Y1[N_NODES * DENSE];
__device__ int   g_deg[N_NODES];
__device__ int   g_rowptr[N_NODES];
__device__ int   g_cursor[N_NODES];
__device__ int   g_col[N_EDGES];
__device__ int   g_bsum[128];
__device__ float g_stats128[2 * DENSE];
__device__ float g_stats64 [2 * HID];
__device__ float g_tf1[2 * DENSE];   // BN affine for width-128 activations
__device__ float g_tfX[2 * HID];     // BN affine for width-64 activations (x)
__device__ float g_tfF[2 * DENSE];   // BN affine for final MLP
__device__ float g_reps[N_GRAPHS * HID];
__device__ float g_T1[N_GRAPHS * DENSE];
__device__ float g_T2[N_GRAPHS * DENSE];

// ---------------- setup: zero degree/stat buffers, identity transform ----
__global__ void k_setup() {
    int t = blockIdx.x * blockDim.x + threadIdx.x;
    if (t < N_NODES)   g_deg[t] = 0;
    if (t < 2 * DENSE) g_stats128[t] = 0.f;
    if (t < 2 * HID)   g_stats64[t]  = 0.f;
    if (t < HID)       { g_tfX[t] = 1.f; g_tfX[HID + t] = 0.f; }
}

// X0 = emb[x_idx]
__global__ void k_embed(const int* __restrict__ x_idx,
                        const float* __restrict__ emb) {
    int t = blockIdx.x * blockDim.x + threadIdx.x;
    if (t < N_NODES * HID) {
        int node = t >> 6, c = t & 63;
        g_Xa[t] = emb[x_idx[node] * HID + c];
    }
}

// ---------------- CSR build (keyed by dst, values = src) ----------------
__global__ void k_hist(const int* __restrict__ ei) {
    int e = blockIdx.x * blockDim.x + threadIdx.x;
    if (e < N_EDGES) atomicAdd(&g_deg[ei[N_EDGES + e]], 1);
}

__global__ void k_scan1() {   // per-block sums of 1024-elem chunks
    __shared__ int ss[256];
    int tid = threadIdx.x;
    int base = blockIdx.x * 1024 + tid * 4;
    int s = 0;
#pragma unroll
    for (int i = 0; i < 4; i++) {
        int idx = base + i;
        if (idx < N_NODES) s += g_deg[idx];
    }
    ss[tid] = s; __syncthreads();
    for (int off = 128; off > 0; off >>= 1) {
        if (tid < off) ss[tid] += ss[tid + off];
        __syncthreads();
    }
    if (tid == 0) g_bsum[blockIdx.x] = ss[0];
}

__global__ void k_scan2(int nblk) {   // serial exclusive scan of 98 values
    if (threadIdx.x == 0) {
        int run = 0;
        for (int i = 0; i < nblk; i++) { int v = g_bsum[i]; g_bsum[i] = run; run += v; }
    }
}

__global__ void k_scan3() {   // in-chunk exclusive scan + offset -> rowptr/cursor
    __shared__ int sc[256];
    int tid = threadIdx.x;
    int base = blockIdx.x * 1024 + tid * 4;
    int d[4]; int s = 0;
#pragma unroll
    for (int i = 0; i < 4; i++) {
        d[i] = (base + i < N_NODES) ? g_deg[base + i] : 0;
        s += d[i];
    }
    sc[tid] = s; __syncthreads();
    for (int off = 1; off < 256; off <<= 1) {
        int v = (tid >= off) ? sc[tid - off] : 0;
        __syncthreads();
        sc[tid] += v;
        __syncthreads();
    }
    int off = g_bsum[blockIdx.x] + sc[tid] - s;   // exclusive prefix
#pragma unroll
    for (int i = 0; i < 4; i++) {
        if (base + i < N_NODES) { g_rowptr[base + i] = off; g_cursor[base + i] = off; off += d[i]; }
    }
}

__global__ void k_fill(const int* __restrict__ ei) {
    int e = blockIdx.x * blockDim.x + threadIdx.x;
    if (e < N_EDGES) {
        int d = ei[N_EDGES + e];
        int p = atomicAdd(&g_cursor[d], 1);
        g_col[p] = ei[e];   // src
    }
}

// ---------------- aggregation: H[n] = (1+eps)*f(X[n]) + sum_nbr f(X[s]) ----
// f(v) = relu?(a*v+b) with (a,b) = g_tfX (BN of previous layer; identity for l=0)
__global__ void __launch_bounds__(256) k_aggr(const float* __restrict__ X,
                                              float* __restrict__ Hout,
                                              const float* __restrict__ epsArr,
                                              int layer, int doRelu) {
    __shared__ float sa[HID], sb[HID];
    int tid = threadIdx.x;
    if (tid < HID)            sa[tid] = g_tfX[tid];
    else if (tid < 2 * HID)   sb[tid - HID] = g_tfX[tid];
    __syncthreads();
    int warp = (blockIdx.x * blockDim.x + tid) >> 5;
    if (warp >= N_NODES) return;
    int lane = tid & 31, c0 = lane * 2;
    float a0 = sa[c0], a1 = sa[c0 + 1], b0 = sb[c0], b1 = sb[c0 + 1];
    float ev = 1.f + epsArr[layer];

    float2 xv = *(const float2*)(X + (size_t)warp * HID + c0);
    float v0 = fmaf(a0, xv.x, b0), v1 = fmaf(a1, xv.y, b1);
    if (doRelu) { v0 = fmaxf(v0, 0.f); v1 = fmaxf(v1, 0.f); }
    float s0 = ev * v0, s1 = ev * v1;

    int start = g_rowptr[warp], deg = g_deg[warp];
    int j = 0;
    for (; j + 1 < deg; j += 2) {
        int n0 = g_col[start + j], n1 = g_col[start + j + 1];
        float2 p = *(const float2*)(X + (size_t)n0 * HID + c0);
        float2 q = *(const float2*)(X + (size_t)n1 * HID + c0);
        float t0 = fmaf(a0, p.x, b0), t1 = fmaf(a1, p.y, b1);
        float u0 = fmaf(a0, q.x, b0), u1 = fmaf(a1, q.y, b1);
        if (doRelu) {
            t0 = fmaxf(t0, 0.f); t1 = fmaxf(t1, 0.f);
            u0 = fmaxf(u0, 0.f); u1 = fmaxf(u1, 0.f);
        }
        s0 += t0 + u0; s1 += t1 + u1;
    }
    if (j < deg) {
        int n0 = g_col[start + j];
        float2 p = *(const float2*)(X + (size_t)n0 * HID + c0);
        float t0 = fmaf(a0, p.x, b0), t1 = fmaf(a1, p.y, b1);
        if (doRelu) { t0 = fmaxf(t0, 0.f); t1 = fmaxf(t1, 0.f); }
        s0 += t0; s1 += t1;
    }
    *(float2*)(Hout + (size_t)warp * HID + c0) = make_float2(s0, s1);
}

// ---------------- GEMM1: Y1[100000,128] = H @ W1[l] (+ column stats) -------
__global__ void __launch_bounds__(256) k_gemm1(const float* __restrict__ A,
                                               const float* __restrict__ W,
                                               float* __restrict__ Y) {
    __shared__ float sW[HID * DENSE];       // 32 KB
    __shared__ float sA[8][HID];
    __shared__ float sS[2 * DENSE];
    int tid = threadIdx.x;
    for (int i = tid; i < HID * DENSE; i += 256) sW[i] = W[i];
    if (tid < 2 * DENSE) sS[tid] = 0.f;
    __syncthreads();
    int warp = tid >> 5, lane = tid & 31;
    int gw = blockIdx.x * 8 + warp, nw = gridDim.x * 8;
    float cs0 = 0, cs1 = 0, cs2 = 0, cs3 = 0, cq0 = 0, cq1 = 0, cq2 = 0, cq3 = 0;
    const float4* sW4 = (const float4*)sW;   // [k][32] float4
    for (int r = gw; r < N_NODES; r += nw) {
        float2 v = *(const float2*)(A + (size_t)r * HID + lane * 2);
        sA[warp][lane * 2] = v.x; sA[warp][lane * 2 + 1] = v.y;
        __syncwarp();
        float x0 = 0, x1 = 0, x2 = 0, x3 = 0;
#pragma unroll
        for (int k = 0; k < HID; k++) {
            float a = sA[warp][k];
            float4 w = sW4[k * 32 + lane];
            x0 = fmaf(a, w.x, x0); x1 = fmaf(a, w.y, x1);
            x2 = fmaf(a, w.z, x2); x3 = fmaf(a, w.w, x3);
        }
        *(float4*)(Y + (size_t)r * DENSE + lane * 4) = make_float4(x0, x1, x2, x3);
        cs0 += x0; cs1 += x1; cs2 += x2; cs3 += x3;
        cq0 += x0 * x0; cq1 += x1 * x1; cq2 += x2 * x2; cq3 += x3 * x3;
        __syncwarp();
    }
    atomicAdd(&sS[lane * 4 + 0], cs0); atomicAdd(&sS[lane * 4 + 1], cs1);
    atomicAdd(&sS[lane * 4 + 2], cs2); atomicAdd(&sS[lane * 4 + 3], cs3);
    atomicAdd(&sS[DENSE + lane * 4 + 0], cq0); atomicAdd(&sS[DENSE + lane * 4 + 1], cq1);
    atomicAdd(&sS[DENSE + lane * 4 + 2], cq2); atomicAdd(&sS[DENSE + lane * 4 + 3], cq3);
    __syncthreads();
    if (tid < 2 * DENSE) atomicAdd(&g_stats128[tid], sS[tid]);
}

// ---------------- finalize BN: stats -> (a,b) affine; rezero stats --------
__global__ void k_fin(float* __restrict__ stats, const float* __restrict__ g,
                      const float* __restrict__ b, float* __restrict__ tf,
                      int width, float invN) {
    int t = threadIdx.x;
    if (t < width) {
        float s = stats[t], q = stats[width + t];
        float m = s * invN;
        float var = q * invN - m * m;
        float rstd = rsqrtf(var + 1e-5f);
        float a = g[t] * rstd;
        tf[t] = a;
        tf[width + t] = b[t] - m * a;
        stats[t] = 0.f; stats[width + t] = 0.f;
    }
}

// ---------------- GEMM2: X'[100000,64] = relu(BN(Y1)) @ W2[l] (+ stats) ---
__global__ void __launch_bounds__(256) k_gemm2(const float* __restrict__ Yin,
                                               const float* __restrict__ W,
                                               float* __restrict__ Xout) {
    __shared__ float sW[DENSE * HID];       // 32 KB
    __shared__ float sA[8][DENSE];
    __shared__ float sTa[DENSE], sTb[DENSE];
    __shared__ float sS[2 * HID];
    int tid = threadIdx.x;
    for (int i = tid; i < DENSE * HID; i += 256) sW[i] = W[i];
    if (tid < DENSE)            sTa[tid] = g_tf1[tid];
    else if (tid < 2 * DENSE)   sTb[tid - DENSE] = g_tf1[tid];
    if (tid < 2 * HID) sS[tid] = 0.f;
    __syncthreads();
    int warp = tid >> 5, lane = tid & 31;
    int gw = blockIdx.x * 8 + warp, nw = gridDim.x * 8;
    float cs0 = 0, cs1 = 0, cq0 = 0, cq1 = 0;
    const float2* sW2 = (const float2*)sW;   // [k][32] float2
    for (int r = gw; r < N_NODES; r += nw) {
        float4 y = *(const float4*)(Yin + (size_t)r * DENSE + lane * 4);
        int k0 = lane * 4;
        sA[warp][k0 + 0] = fmaxf(fmaf(sTa[k0 + 0], y.x, sTb[k0 + 0]), 0.f);
        sA[warp][k0 + 1] = fmaxf(fmaf(sTa[k0 + 1], y.y, sTb[k0 + 1]), 0.f);
        sA[warp][k0 + 2] = fmaxf(fmaf(sTa[k0 + 2], y.z, sTb[k0 + 2]), 0.f);
        sA[warp][k0 + 3] = fmaxf(fmaf(sTa[k0 + 3], y.w, sTb[k0 + 3]), 0.f);
        __syncwarp();
        float x0 = 0, x1 = 0;
#pragma unroll 32
        for (int k = 0; k < DENSE; k++) {
            float a = sA[warp][k];
            float2 w = sW2[k * 32 + lane];
            x0 = fmaf(a, w.x, x0); x1 = fmaf(a, w.y, x1);
        }
        *(float2*)(Xout + (size_t)r * HID + lane * 2) = make_float2(x0, x1);
        cs0 += x0; cs1 += x1; cq0 += x0 * x0; cq1 += x1 * x1;
        __syncwarp();
    }
    atomicAdd(&sS[lane * 2 + 0], cs0); atomicAdd(&sS[lane * 2 + 1], cs1);
    atomicAdd(&sS[HID + lane * 2 + 0], cq0); atomicAdd(&sS[HID + lane * 2 + 1], cq1);
    __syncthreads();
    if (tid < 2 * HID) atomicAdd(&g_stats64[tid], sS[tid]);
}

// ---------------- global mean pool per graph (batch is sorted) ------------
__global__ void k_pool(const float* __restrict__ X, const int* __restrict__ batch) {
    __shared__ float sa[HID], sb[HID];
    __shared__ float sred[4][HID];
    __shared__ int s_lo, s_hi;
    int tid = threadIdx.x, g = blockIdx.x;
    if (tid < HID)          sa[tid] = g_tfX[tid];
    else if (tid < 2 * HID) sb[tid - HID] = g_tfX[tid];
    if (tid == 0) {
        int lo = 0, hi = N_NODES;
        while (lo < hi) { int mid = (lo + hi) >> 1; if (batch[mid] < g) lo = mid + 1; else hi = mid; }
        s_lo = lo;
        lo = 0; hi = N_NODES; int gg = g + 1;
        while (lo < hi) { int mid = (lo + hi) >> 1; if (batch[mid] < gg) lo = mid + 1; else hi = mid; }
        s_hi = lo;
    }
    __syncthreads();
    int c = tid & 63, rg = tid >> 6;
    float acc = 0.f;
    for (int r = s_lo + rg; r < s_hi; r += 4) {
        float v = fmaf(sa[c], X[(size_t)r * HID + c], sb[c]);
        acc += fmaxf(v, 0.f);
    }
    sred[rg][c] = acc; __syncthreads();
    if (tid < HID) {
        float s = sred[0][c] + sred[1][c] + sred[2][c] + sred[3][c];
        int cnt = s_hi - s_lo;
        g_reps[g * HID + c] = s / (float)(cnt > 0 ? cnt : 1);
    }
}

// ---------------- tiny final-MLP GEMMs (M = 128 graphs) -------------------
__global__ void kf_gemm(const float* __restrict__ A, const float* __restrict__ W,
                        float* __restrict__ out, float* __restrict__ stats,
                        const float* __restrict__ tf, int K, int N) {
    int r = blockIdx.x, n = threadIdx.x;
    float acc = 0.f;
    for (int k = 0; k < K; k++) {
        float av = A[r * K + k];
        if (tf) av = fmaxf(fmaf(tf[k], av, tf[K + k]), 0.f);
        acc = fmaf(av, W[k * N + n], acc);
    }
    out[r * N + n] = acc;
    atomicAdd(&stats[n], acc);
    atomicAdd(&stats[N + n], acc * acc);
}

__global__ void kf_out(const float* __restrict__ T2v, const float* __restrict__ Wlin,
                       const float* __restrict__ blin, float* __restrict__ out) {
    int r = blockIdx.x, o = threadIdx.x;
    if (o < OUTD) {
        float acc = blin[o];
        for (int k = 0; k < DENSE; k++) {
            float av = fmaxf(fmaf(g_tfF[k], T2v[r * DENSE + k], g_tfF[DENSE + k]), 0.f);
            acc = fmaf(av, Wlin[k * OUTD + o], acc);
        }
        out[r * OUTD + o] = acc;
    }
}

// ---------------- launcher ------------------------------------------------
extern "C" void kernel_launch(void* const* d_in, const int* in_sizes, int n_in,
                              void* d_out, int out_size) {
    (void)in_sizes; (void)n_in; (void)out_size;
    const int*   x_idx = (const int*)d_in[0];
    const int*   ei    = (const int*)d_in[1];
    const int*   batch = (const int*)d_in[2];
    const float* emb   = (const float*)d_in[3];
    const float* eps   = (const float*)d_in[4];
    const float* W1    = (const float*)d_in[5];
    const float* g1    = (const float*)d_in[6];
    const float* b1    = (const float*)d_in[7];
    const float* W2    = (const float*)d_in[8];
    const float* g2    = (const float*)d_in[9];
    const float* b2    = (const float*)d_in[10];
    const float* Wf1   = (const float*)d_in[11];
    const float* gf1   = (const float*)d_in[12];
    const float* bf1   = (const float*)d_in[13];
    const float* Wf2   = (const float*)d_in[14];
    const float* gf2   = (const float*)d_in[15];
    const float* bf2   = (const float*)d_in[16];
    const float* Wlin  = (const float*)d_in[17];
    const float* blin  = (const float*)d_in[18];
    float* out = (float*)d_out;

    float *Xa, *Xb, *H, *Y1, *s128, *s64, *tf1x, *tfX, *reps, *T1, *T2, *tfF;
    cudaGetSymbolAddress((void**)&Xa,   g_Xa);
    cudaGetSymbolAddress((void**)&Xb,   g_Xb);
    cudaGetSymbolAddress((void**)&H,    g_H);
    cudaGetSymbolAddress((void**)&Y1,   g_Y1);
    cudaGetSymbolAddress((void**)&s128, g_stats128);
    cudaGetSymbolAddress((void**)&s64,  g_stats64);
    cudaGetSymbolAddress((void**)&tf1x, g_tf1);
    cudaGetSymbolAddress((void**)&tfX,  g_tfX);
    cudaGetSymbolAddress((void**)&reps, g_reps);
    cudaGetSymbolAddress((void**)&T1,   g_T1);
    cudaGetSymbolAddress((void**)&T2,   g_T2);
    cudaGetSymbolAddress((void**)&tfF,  g_tfF);

    k_setup<<<(N_NODES + 255) / 256, 256>>>();
    k_embed<<<(N_NODES * HID + 255) / 256, 256>>>(x_idx, emb);
    k_hist <<<(N_EDGES + 255) / 256, 256>>>(ei);
    k_scan1<<<SCAN_NB, 256>>>();
    k_scan2<<<1, 32>>>(SCAN_NB);
    k_scan3<<<SCAN_NB, 256>>>();
    k_fill <<<(N_EDGES + 255) / 256, 256>>>(ei);

    const int GEMM_GRID = 444;
    float* Xcur = Xa; float* Xnext = Xb;
    const float invN = 1.f / (float)N_NODES;
    for (int l = 0; l < 4; l++) {
        k_aggr<<<(N_NODES * 32 + 255) / 256, 256>>>(Xcur, H, eps, l, l > 0 ? 1 : 0);
        k_gemm1<<<GEMM_GRID, 256>>>(H, W1 + (size_t)l * HID * DENSE, Y1);
        k_fin<<<1, DENSE>>>(s128, g1 + l * DENSE, b1 + l * DENSE, tf1x, DENSE, invN);
        k_gemm2<<<GEMM_GRID, 256>>>(Y1, W2 + (size_t)l * DENSE * HID, Xnext);
        k_fin<<<1, HID>>>(s64, g2 + l * HID, b2 + l * HID, tfX, HID, invN);
        float* t = Xcur; Xcur = Xnext; Xnext = t;
    }
    k_pool<<<N_GRAPHS, 256>>>(Xcur, batch);

    const float invG = 1.f / (float)N_GRAPHS;
    kf_gemm<<<N_GRAPHS, DENSE>>>(reps, Wf1, T1, s128, (const float*)0, HID, DENSE);
    k_fin<<<1, DENSE>>>(s128, gf1, bf1, tfF, DENSE, invG);
    kf_gemm<<<N_GRAPHS, DENSE>>>(T1, Wf2, T2, s128, tfF, DENSE, DENSE);
    k_fin<<<1, DENSE>>>(s128, gf2, bf2, tfF, DENSE, invG);
    kf_out<<<N_GRAPHS, 32>>>(T2, Wlin, blin, out);
}

// round 2
// speedup vs baseline: 1.5068x; 1.5068x over previous
#include <cuda_runtime.h>

#define N_NODES 100000
#define N_EDGES 1600000
#define HID 64
#define DENSE 128
#define OUTD 10
#define N_GRAPHS 128
#define SCAN_NB 98   // ceil(100000/1024)

// ---------------- device scratch (no allocations allowed) ----------------
__device__ __align__(16) float g_Xa[N_NODES * HID];
__device__ __align__(16) float g_Xb[N_NODES * HID];
__device__ __align__(16) float g_H [N_NODES * HID];
__device__ __align__(16) float g_Y1[N_NODES * DENSE];
__device__ int   g_deg[N_NODES];
__device__ int   g_rowptr[N_NODES];
__device__ int   g_cursor[N_NODES];
__device__ int   g_col[N_EDGES];
__device__ int   g_bsum[128];
__device__ __align__(16) float g_stats128[2 * DENSE];
__device__ __align__(16) float g_stats64 [2 * HID];
__device__ __align__(16) float g_tf1[2 * DENSE];   // BN affine width-128
__device__ __align__(16) float g_tfX[2 * HID];     // BN affine width-64 (x)
__device__ __align__(16) float g_tfF[2 * DENSE];   // BN affine final MLP
__device__ __align__(16) float g_reps[N_GRAPHS * HID];
__device__ __align__(16) float g_T1[N_GRAPHS * DENSE];
__device__ __align__(16) float g_T2[N_GRAPHS * DENSE];

// ---------------- setup: zero degree/stat buffers ------------------------
__global__ void k_setup() {
    int t = blockIdx.x * blockDim.x + threadIdx.x;
    if (t < N_NODES)   g_deg[t] = 0;
    if (t < 2 * DENSE) g_stats128[t] = 0.f;
    if (t < 2 * HID)   g_stats64[t]  = 0.f;
}

// ---------------- CSR build (keyed by dst, values = src) ----------------
__global__ void k_hist(const int* __restrict__ ei) {
    int e = blockIdx.x * blockDim.x + threadIdx.x;
    if (e < N_EDGES) atomicAdd(&g_deg[ei[N_EDGES + e]], 1);
}

__global__ void k_scan1() {
    __shared__ int ss[256];
    int tid = threadIdx.x;
    int base = blockIdx.x * 1024 + tid * 4;
    int s = 0;
#pragma unroll
    for (int i = 0; i < 4; i++) {
        int idx = base + i;
        if (idx < N_NODES) s += g_deg[idx];
    }
    ss[tid] = s; __syncthreads();
    for (int off = 128; off > 0; off >>= 1) {
        if (tid < off) ss[tid] += ss[tid + off];
        __syncthreads();
    }
    if (tid == 0) g_bsum[blockIdx.x] = ss[0];
}

__global__ void k_scan2(int nblk) {
    if (threadIdx.x == 0) {
        int run = 0;
        for (int i = 0; i < nblk; i++) { int v = g_bsum[i]; g_bsum[i] = run; run += v; }
    }
}

__global__ void k_scan3() {
    __shared__ int sc[256];
    int tid = threadIdx.x;
    int base = blockIdx.x * 1024 + tid * 4;
    int d[4]; int s = 0;
#pragma unroll
    for (int i = 0; i < 4; i++) {
        d[i] = (base + i < N_NODES) ? g_deg[base + i] : 0;
        s += d[i];
    }
    sc[tid] = s; __syncthreads();
    for (int off = 1; off < 256; off <<= 1) {
        int v = (tid >= off) ? sc[tid - off] : 0;
        __syncthreads();
        sc[tid] += v;
        __syncthreads();
    }
    int off = g_bsum[blockIdx.x] + sc[tid] - s;
#pragma unroll
    for (int i = 0; i < 4; i++) {
        if (base + i < N_NODES) { g_rowptr[base + i] = off; g_cursor[base + i] = off; off += d[i]; }
    }
}

__global__ void k_fill(const int* __restrict__ ei) {
    int e = blockIdx.x * blockDim.x + threadIdx.x;
    if (e < N_EDGES) {
        int d = ei[N_EDGES + e];
        int p = atomicAdd(&g_cursor[d], 1);
        g_col[p] = ei[e];   // src
    }
}

// ---------------- layer-0 aggregation fused with embedding ---------------
// H[n] = (1+eps0)*emb[idx[n]] + sum_nbr emb[idx[s]]
__global__ void __launch_bounds__(256) k_aggr0(const int* __restrict__ x_idx,
                                               const float* __restrict__ emb,
                                               const float* __restrict__ epsArr,
                                               float* __restrict__ Hout) {
    int warp = (blockIdx.x * blockDim.x + threadIdx.x) >> 5;
    if (warp >= N_NODES) return;
    int lane = threadIdx.x & 31, c0 = lane * 2;
    float ev = 1.f + epsArr[0];
    int self = __ldg(&x_idx[warp]);
    float2 xv = *(const float2*)(emb + (size_t)self * HID + c0);
    float s0 = ev * xv.x, s1 = ev * xv.y;
    int start = g_rowptr[warp], deg = g_deg[warp];
    int j = 0;
    for (; j + 1 < deg; j += 2) {
        int n0 = __ldg(&x_idx[g_col[start + j]]);
        int n1 = __ldg(&x_idx[g_col[start + j + 1]]);
        float2 p = *(const float2*)(emb + (size_t)n0 * HID + c0);
        float2 q = *(const float2*)(emb + (size_t)n1 * HID + c0);
        s0 += p.x + q.x; s1 += p.y + q.y;
    }
    if (j < deg) {
        int n0 = __ldg(&x_idx[g_col[start + j]]);
        float2 p = *(const float2*)(emb + (size_t)n0 * HID + c0);
        s0 += p.x; s1 += p.y;
    }
    *(float2*)(Hout + (size_t)warp * HID + c0) = make_float2(s0, s1);
}

// ---------------- aggregation l>=1: f = relu(BN affine) ------------------
__global__ void __launch_bounds__(256) k_aggr(const float* __restrict__ X,
                                              float* __restrict__ Hout,
                                              const float* __restrict__ epsArr,
                                              int layer) {
    __shared__ float sa[HID], sb[HID];
    int tid = threadIdx.x;
    if (tid < HID)            sa[tid] = g_tfX[tid];
    else if (tid < 2 * HID)   sb[tid - HID] = g_tfX[tid];
    __syncthreads();
    int warp = (blockIdx.x * blockDim.x + tid) >> 5;
    if (warp >= N_NODES) return;
    int lane = tid & 31, c0 = lane * 2;
    float a0 = sa[c0], a1 = sa[c0 + 1], b0 = sb[c0], b1 = sb[c0 + 1];
    float ev = 1.f + epsArr[layer];

    float2 xv = *(const float2*)(X + (size_t)warp * HID + c0);
    float s0 = ev * fmaxf(fmaf(a0, xv.x, b0), 0.f);
    float s1 = ev * fmaxf(fmaf(a1, xv.y, b1), 0.f);

    int start = g_rowptr[warp], deg = g_deg[warp];
    int j = 0;
    for (; j + 1 < deg; j += 2) {
        int n0 = g_col[start + j], n1 = g_col[start + j + 1];
        float2 p = *(const float2*)(X + (size_t)n0 * HID + c0);
        float2 q = *(const float2*)(X + (size_t)n1 * HID + c0);
        s0 += fmaxf(fmaf(a0, p.x, b0), 0.f) + fmaxf(fmaf(a0, q.x, b0), 0.f);
        s1 += fmaxf(fmaf(a1, p.y, b1), 0.f) + fmaxf(fmaf(a1, q.y, b1), 0.f);
    }
    if (j < deg) {
        int n0 = g_col[start + j];
        float2 p = *(const float2*)(X + (size_t)n0 * HID + c0);
        s0 += fmaxf(fmaf(a0, p.x, b0), 0.f);
        s1 += fmaxf(fmaf(a1, p.y, b1), 0.f);
    }
    *(float2*)(Hout + (size_t)warp * HID + c0) = make_float2(s0, s1);
}

// ---------------- GEMM1: Y1[100000,128] = H @ W1[l]  (register tiled) ----
// block tile 128 rows x 128 cols, K=64 fully resident; thread tile 8x8.
#define G1_SMEM_FLOATS (128*64 + 64*128 + 2*128)
__global__ void __launch_bounds__(256, 2) k_gemm1(const float* __restrict__ A,
                                                  const float* __restrict__ W,
                                                  float* __restrict__ Y) {
    extern __shared__ float sm[];
    float* sA = sm;                 // [128][64] row-major
    float* sW = sm + 128 * 64;      // [64][128] k-major
    float* sS = sW + 64 * 128;      // [256] col stats
    int t = threadIdx.x;
    int row0 = blockIdx.x * 128;

    {   // W tile: 8192 floats
        const float4* W4 = (const float4*)W;
        float4* sW4 = (float4*)sW;
#pragma unroll
        for (int i = 0; i < 8; i++) sW4[t + i * 256] = W4[t + i * 256];
    }
    {   // A tile: 128 rows x 64 k
        int r = t >> 1, kh = (t & 1) * 32;
        int gr = row0 + r;
        float4* dst = (float4*)(sA + r * 64 + kh);
        if (gr < N_NODES) {
            const float4* src = (const float4*)(A + (size_t)gr * 64 + kh);
#pragma unroll
            for (int i = 0; i < 8; i++) dst[i] = src[i];
        } else {
#pragma unroll
            for (int i = 0; i < 8; i++) dst[i] = make_float4(0.f, 0.f, 0.f, 0.f);
        }
    }
    sS[t] = 0.f;
    __syncthreads();

    int tx = t & 15, ty = t >> 4;
    const float* aBase = sA + ty * 8 * 64;
    const float4* w4 = (const float4*)sW;

    float acc[8][8];
#pragma unroll
    for (int i = 0; i < 8; i++)
#pragma unroll
        for (int j = 0; j < 8; j++) acc[i][j] = 0.f;

#pragma unroll 8
    for (int k = 0; k < 64; k++) {
        float4 wa = w4[k * 32 + tx];
        float4 wb = w4[k * 32 + 16 + tx];
        float av[8];
#pragma unroll
        for (int i = 0; i < 8; i++) av[i] = aBase[i * 64 + k];
#pragma unroll
        for (int i = 0; i < 8; i++) {
            acc[i][0] = fmaf(av[i], wa.x, acc[i][0]);
            acc[i][1] = fmaf(av[i], wa.y, acc[i][1]);
            acc[i][2] = fmaf(av[i], wa.z, acc[i][2]);
            acc[i][3] = fmaf(av[i], wa.w, acc[i][3]);
            acc[i][4] = fmaf(av[i], wb.x, acc[i][4]);
            acc[i][5] = fmaf(av[i], wb.y, acc[i][5]);
            acc[i][6] = fmaf(av[i], wb.z, acc[i][6]);
            acc[i][7] = fmaf(av[i], wb.w, acc[i][7]);
        }
    }

    float cs[8], cq[8];
#pragma unroll
    for (int j = 0; j < 8; j++) { cs[j] = 0.f; cq[j] = 0.f; }
#pragma unroll
    for (int i = 0; i < 8; i++) {
        int gr = row0 + ty * 8 + i;
        if (gr < N_NODES) {
            *(float4*)(Y + (size_t)gr * 128 + tx * 4) =
                make_float4(acc[i][0], acc[i][1], acc[i][2], acc[i][3]);
            *(float4*)(Y + (size_t)gr * 128 + 64 + tx * 4) =
                make_float4(acc[i][4], acc[i][5], acc[i][6], acc[i][7]);
        }
#pragma unroll
        for (int j = 0; j < 8; j++) { cs[j] += acc[i][j]; cq[j] += acc[i][j] * acc[i][j]; }
    }
#pragma unroll
    for (int j = 0; j < 4; j++) {
        atomicAdd(&sS[tx * 4 + j], cs[j]);
        atomicAdd(&sS[128 + tx * 4 + j], cq[j]);
        atomicAdd(&sS[64 + tx * 4 + j], cs[4 + j]);
        atomicAdd(&sS[128 + 64 + tx * 4 + j], cq[4 + j]);
    }
    __syncthreads();
    atomicAdd(&g_stats128[t], sS[t]);
}

// ---------------- finalize BN: stats -> (a,b) affine; rezero stats --------
__global__ void k_fin(float* __restrict__ stats, const float* __restrict__ g,
                      const float* __restrict__ b, float* __restrict__ tf,
                      int width, float invN) {
    int t = threadIdx.x;
    if (t < width) {
        float s = stats[t], q = stats[width + t];
        float m = s * invN;
        float var = q * invN - m * m;
        float rstd = rsqrtf(var + 1e-5f);
        float a = g[t] * rstd;
        tf[t] = a;
        tf[width + t] = b[t] - m * a;
        stats[t] = 0.f; stats[width + t] = 0.f;
    }
}

// ---------------- GEMM2: X'[100000,64] = relu(BN(Y1)) @ W2[l] -------------
// block tile 128 rows x 64 cols, K=128; thread tile 8x4.
#define G2_SMEM_FLOATS (128*128 + 128*64 + 2*64)
__global__ void __launch_bounds__(256, 2) k_gemm2(const float* __restrict__ Yin,
                                                  const float* __restrict__ W,
                                                  float* __restrict__ Xout) {
    extern __shared__ float sm[];
    float* sA = sm;                  // [128][128]
    float* sW = sm + 128 * 128;      // [128][64]
    float* sS = sW + 128 * 64;       // [128]
    int t = threadIdx.x;
    int row0 = blockIdx.x * 128;

    {   // W tile: 8192 floats
        const float4* W4 = (const float4*)W;
        float4* sW4 = (float4*)sW;
#pragma unroll
        for (int i = 0; i < 8; i++) sW4[t + i * 256] = W4[t + i * 256];
    }
    {   // A tile with BN+relu transform
        int r = t >> 1, kh = (t & 1) * 64;
        int gr = row0 + r;
        float4* dst = (float4*)(sA + r * 128 + kh);
        if (gr < N_NODES) {
            const float4* src = (const float4*)(Yin + (size_t)gr * 128 + kh);
#pragma unroll
            for (int i = 0; i < 16; i++) {
                float4 y = src[i];
                float4 ta = *(const float4*)(g_tf1 + kh + i * 4);
                float4 tb = *(const float4*)(g_tf1 + 128 + kh + i * 4);
                float4 v;
                v.x = fmaxf(fmaf(ta.x, y.x, tb.x), 0.f);
                v.y = fmaxf(fmaf(ta.y, y.y, tb.y), 0.f);
                v.z = fmaxf(fmaf(ta.z, y.z, tb.z), 0.f);
                v.w = fmaxf(fmaf(ta.w, y.w, tb.w), 0.f);
                dst[i] = v;
            }
        } else {
#pragma unroll
            for (int i = 0; i < 16; i++) dst[i] = make_float4(0.f, 0.f, 0.f, 0.f);
        }
    }
    if (t < 128) sS[t] = 0.f;
    __syncthreads();

    int tx = t & 15, ty = t >> 4;
    const float* aBase = sA + ty * 8 * 128;
    const float4* w4 = (const float4*)sW;

    float acc[8][4];
#pragma unroll
    for (int i = 0; i < 8; i++)
#pragma unroll
        for (int j = 0; j < 4; j++) acc[i][j] = 0.f;

#pragma unroll 8
    for (int k = 0; k < 128; k++) {
        float4 w = w4[k * 16 + tx];
        float av[8];
#pragma unroll
        for (int i = 0; i < 8; i++) av[i] = aBase[i * 128 + k];
#pragma unroll
        for (int i = 0; i < 8; i++) {
            acc[i][0] = fmaf(av[i], w.x, acc[i][0]);
            acc[i][1] = fmaf(av[i], w.y, acc[i][1]);
            acc[i][2] = fmaf(av[i], w.z, acc[i][2]);
            acc[i][3] = fmaf(av[i], w.w, acc[i][3]);
        }
    }

    float cs[4] = {0.f, 0.f, 0.f, 0.f}, cq[4] = {0.f, 0.f, 0.f, 0.f};
#pragma unroll
    for (int i = 0; i < 8; i++) {
        int gr = row0 + ty * 8 + i;
        if (gr < N_NODES)
            *(float4*)(Xout + (size_t)gr * 64 + tx * 4) =
                make_float4(acc[i][0], acc[i][1], acc[i][2], acc[i][3]);
#pragma unroll
        for (int j = 0; j < 4; j++) { cs[j] += acc[i][j]; cq[j] += acc[i][j] * acc[i][j]; }
    }
#pragma unroll
    for (int j = 0; j < 4; j++) {
        atomicAdd(&sS[tx * 4 + j], cs[j]);
        atomicAdd(&sS[64 + tx * 4 + j], cq[j]);
    }
    __syncthreads();
    if (t < 128) atomicAdd(&g_stats64[t], sS[t]);
}

// ---------------- global mean pool per graph (batch is sorted) ------------
__global__ void k_pool(const float* __restrict__ X, const int* __restrict__ batch) {
    __shared__ float sa[HID], sb[HID];
    __shared__ float sred[4][HID];
    __shared__ int s_lo, s_hi;
    int tid = threadIdx.x, g = blockIdx.x;
    if (tid < HID)          sa[tid] = g_tfX[tid];
    else if (tid < 2 * HID) sb[tid - HID] = g_tfX[tid];
    if (tid == 0) {
        int lo = 0, hi = N_NODES;
        while (lo < hi) { int mid = (lo + hi) >> 1; if (batch[mid] < g) lo = mid + 1; else hi = mid; }
        s_lo = lo;
        lo = 0; hi = N_NODES; int gg = g + 1;
        while (lo < hi) { int mid = (lo + hi) >> 1; if (batch[mid] < gg) lo = mid + 1; else hi = mid; }
        s_hi = lo;
    }
    __syncthreads();
    int c = tid & 63, rg = tid >> 6;
    float acc = 0.f;
    for (int r = s_lo + rg; r < s_hi; r += 4) {
        float v = fmaf(sa[c], X[(size_t)r * HID + c], sb[c]);
        acc += fmaxf(v, 0.f);
    }
    sred[rg][c] = acc; __syncthreads();
    if (tid < HID) {
        float s = sred[0][c] + sred[1][c] + sred[2][c] + sred[3][c];
        int cnt = s_hi - s_lo;
        g_reps[g * HID + c] = s / (float)(cnt > 0 ? cnt : 1);
    }
}

// ---------------- tiny final-MLP GEMMs (M = 128 graphs) -------------------
__global__ void kf_gemm(const float* __restrict__ A, const float* __restrict__ W,
                        float* __restrict__ out, float* __restrict__ stats,
                        const float* __restrict__ tf, int K, int N) {
    int r = blockIdx.x, n = threadIdx.x;
    float acc = 0.f;
    for (int k = 0; k < K; k++) {
        float av = A[r * K + k];
        if (tf) av = fmaxf(fmaf(tf[k], av, tf[K + k]), 0.f);
        acc = fmaf(av, W[k * N + n], acc);
    }
    out[r * N + n] = acc;
    atomicAdd(&stats[n], acc);
    atomicAdd(&stats[N + n], acc * acc);
}

__global__ void kf_out(const float* __restrict__ T2v, const float* __restrict__ Wlin,
                       const float* __restrict__ blin, float* __restrict__ out) {
    int r = blockIdx.x, o = threadIdx.x;
    if (o < OUTD) {
        float acc = blin[o];
        for (int k = 0; k < DENSE; k++) {
            float av = fmaxf(fmaf(g_tfF[k], T2v[r * DENSE + k], g_tfF[DENSE + k]), 0.f);
            acc = fmaf(av, Wlin[k * OUTD + o], acc);
        }
        out[r * OUTD + o] = acc;
    }
}

// ---------------- launcher ------------------------------------------------
extern "C" void kernel_launch(void* const* d_in, const int* in_sizes, int n_in,
                              void* d_out, int out_size) {
    (void)in_sizes; (void)n_in; (void)out_size;
    const int*   x_idx = (const int*)d_in[0];
    const int*   ei    = (const int*)d_in[1];
    const int*   batch = (const int*)d_in[2];
    const float* emb   = (const float*)d_in[3];
    const float* eps   = (const float*)d_in[4];
    const float* W1    = (const float*)d_in[5];
    const float* g1    = (const float*)d_in[6];
    const float* b1    = (const float*)d_in[7];
    const float* W2    = (const float*)d_in[8];
    const float* g2    = (const float*)d_in[9];
    const float* b2    = (const float*)d_in[10];
    const float* Wf1   = (const float*)d_in[11];
    const float* gf1   = (const float*)d_in[12];
    const float* bf1   = (const float*)d_in[13];
    const float* Wf2   = (const float*)d_in[14];
    const float* gf2   = (const float*)d_in[15];
    const float* bf2   = (const float*)d_in[16];
    const float* Wlin  = (const float*)d_in[17];
    const float* blin  = (const float*)d_in[18];
    float* out = (float*)d_out;

    float *Xa, *Xb, *H, *Y1, *s128, *s64, *tf1x, *tfX, *reps, *T1, *T2, *tfF;
    cudaGetSymbolAddress((void**)&Xa,   g_Xa);
    cudaGetSymbolAddress((void**)&Xb,   g_Xb);
    cudaGetSymbolAddress((void**)&H,    g_H);
    cudaGetSymbolAddress((void**)&Y1,   g_Y1);
    cudaGetSymbolAddress((void**)&s128, g_stats128);
    cudaGetSymbolAddress((void**)&s64,  g_stats64);
    cudaGetSymbolAddress((void**)&tf1x, g_tf1);
    cudaGetSymbolAddress((void**)&tfX,  g_tfX);
    cudaGetSymbolAddress((void**)&reps, g_reps);
    cudaGetSymbolAddress((void**)&T1,   g_T1);
    cudaGetSymbolAddress((void**)&T2,   g_T2);
    cudaGetSymbolAddress((void**)&tfF,  g_tfF);

    static const size_t G1_BYTES = G1_SMEM_FLOATS * sizeof(float);
    static const size_t G2_BYTES = G2_SMEM_FLOATS * sizeof(float);
    cudaFuncSetAttribute(k_gemm1, cudaFuncAttributeMaxDynamicSharedMemorySize, (int)G1_BYTES);
    cudaFuncSetAttribute(k_gemm2, cudaFuncAttributeMaxDynamicSharedMemorySize, (int)G2_BYTES);

    k_setup<<<(N_NODES + 255) / 256, 256>>>();
    k_hist <<<(N_EDGES + 255) / 256, 256>>>(ei);
    k_scan1<<<SCAN_NB, 256>>>();
    k_scan2<<<1, 32>>>(SCAN_NB);
    k_scan3<<<SCAN_NB, 256>>>();
    k_fill <<<(N_EDGES + 255) / 256, 256>>>(ei);

    const int GEMM_GRID = (N_NODES + 127) / 128;   // 782
    float* Xcur = Xa; float* Xnext = Xb;
    const float invN = 1.f / (float)N_NODES;
    for (int l = 0; l < 4; l++) {
        if (l == 0)
            k_aggr0<<<(N_NODES * 32 + 255) / 256, 256>>>(x_idx, emb, eps, H);
        else
            k_aggr<<<(N_NODES * 32 + 255) / 256, 256>>>(Xcur, H, eps, l);
        k_gemm1<<<GEMM_GRID, 256, G1_BYTES>>>(H, W1 + (size_t)l * HID * DENSE, Y1);
        k_fin<<<1, DENSE>>>(s128, g1 + l * DENSE, b1 + l * DENSE, tf1x, DENSE, invN);
        k_gemm2<<<GEMM_GRID, 256, G2_BYTES>>>(Y1, W2 + (size_t)l * DENSE * HID, Xnext);
        k_fin<<<1, HID>>>(s64, g2 + l * HID, b2 + l * HID, tfX, HID, invN);
        float* t = Xcur; Xcur = Xnext; Xnext = t;
    }
    k_pool<<<N_GRAPHS, 256>>>(Xcur, batch);

    const float invG = 1.f / (float)N_GRAPHS;
    kf_gemm<<<N_GRAPHS, DENSE>>>(reps, Wf1, T1, s128, (const float*)0, HID, DENSE);
    k_fin<<<1, DENSE>>>(s128, gf1, bf1, tfF, DENSE, invG);
    kf_gemm<<<N_GRAPHS, DENSE>>>(T1, Wf2, T2, s128, tfF, DENSE, DENSE);
    k_fin<<<1, DENSE>>>(s128, gf2, bf2, tfF, DENSE, invG);
    kf_out<<<N_GRAPHS, 32>>>(T2, Wlin, blin, out);
}

// round 3
// speedup vs baseline: 1.6583x; 1.1005x over previous
#include <cuda_runtime.h>

#define N_NODES 100000
#define N_EDGES 1600000
#define HID 64
#define DENSE 128
#define OUTD 10
#define N_GRAPHS 128
#define SCAN_NB 98   // ceil(100000/1024)
#define INVN (1.f / (float)N_NODES)

// ---------------- packed f32x2 helpers (sm_100a FFMA2 path) ---------------
__device__ __forceinline__ unsigned long long pk2(float lo, float hi) {
    unsigned long long r;
    asm("mov.b64 %0,{%1,%2};" : "=l"(r) : "f"(lo), "f"(hi));
    return r;
}
__device__ __forceinline__ void fma2(unsigned long long& d,
                                     unsigned long long a, unsigned long long b) {
    asm("fma.rn.f32x2 %0,%1,%2,%0;" : "+l"(d) : "l"(a), "l"(b));
}
__device__ __forceinline__ float2 up2(unsigned long long v) {
    float2 r;
    asm("mov.b64 {%0,%1},%2;" : "=f"(r.x), "=f"(r.y) : "l"(v));
    return r;
}

// ---------------- device scratch (no allocations allowed) ----------------
__device__ __align__(16) float g_Xa[N_NODES * HID];
__device__ __align__(16) float g_Xb[N_NODES * HID];
__device__ __align__(16) float g_H [N_NODES * HID];
__device__ __align__(16) float g_Y1[N_NODES * DENSE];
__device__ int   g_deg[N_NODES];
__device__ int   g_rowptr[N_NODES];
__device__ int   g_cursor[N_NODES];
__device__ int   g_col[N_EDGES];
__device__ int   g_bsum[128];
__device__ __align__(16) float g_stats128[4 * 2 * DENSE];  // per-layer
__device__ __align__(16) float g_stats64 [4 * 2 * HID];    // per-layer
__device__ __align__(16) float g_statsF[2 * DENSE];
__device__ __align__(16) float g_tfF[2 * DENSE];
__device__ __align__(16) float g_reps[N_GRAPHS * HID];
__device__ __align__(16) float g_T1[N_GRAPHS * DENSE];
__device__ __align__(16) float g_T2[N_GRAPHS * DENSE];

// ---------------- setup: zero degree/stat buffers ------------------------
__global__ void k_setup() {
    int t = blockIdx.x * blockDim.x + threadIdx.x;
    if (t < N_NODES)          g_deg[t] = 0;
    if (t < 4 * 2 * DENSE)    g_stats128[t] = 0.f;
    if (t < 4 * 2 * HID)      g_stats64[t]  = 0.f;
    if (t < 2 * DENSE)        g_statsF[t] = 0.f;
}

// ---------------- CSR build (keyed by dst, values = src) ----------------
__global__ void k_hist(const int* __restrict__ ei) {
    int e = blockIdx.x * blockDim.x + threadIdx.x;
    if (e < N_EDGES) atomicAdd(&g_deg[ei[N_EDGES + e]], 1);
}

__global__ void k_scan1() {
    __shared__ int ss[256];
    int tid = threadIdx.x;
    int base = blockIdx.x * 1024 + tid * 4;
    int s = 0;
#pragma unroll
    for (int i = 0; i < 4; i++) {
        int idx = base + i;
        if (idx < N_NODES) s += g_deg[idx];
    }
    ss[tid] = s; __syncthreads();
    for (int off = 128; off > 0; off >>= 1) {
        if (tid < off) ss[tid] += ss[tid + off];
        __syncthreads();
    }
    if (tid == 0) g_bsum[blockIdx.x] = ss[0];
}

__global__ void k_scan2(int nblk) {   // parallel exclusive scan of <=128 vals
    __shared__ int ws[4];
    int t = threadIdx.x, lane = t & 31, w = t >> 5;
    int orig = (t < nblk) ? g_bsum[t] : 0;
    int v = orig;
#pragma unroll
    for (int o = 1; o < 32; o <<= 1) {
        int n = __shfl_up_sync(0xFFFFFFFFu, v, o);
        if (lane >= o) v += n;
    }
    if (lane == 31) ws[w] = v;
    __syncthreads();
    int add = 0;
    for (int i = 0; i < w; i++) add += ws[i];
    v += add;
    if (t < nblk) g_bsum[t] = v - orig;   // exclusive
}

__global__ void k_scan3() {
    __shared__ int sc[256];
    int tid = threadIdx.x;
    int base = blockIdx.x * 1024 + tid * 4;
    int d[4]; int s = 0;
#pragma unroll
    for (int i = 0; i < 4; i++) {
        d[i] = (base + i < N_NODES) ? g_deg[base + i] : 0;
        s += d[i];
    }
    sc[tid] = s; __syncthreads();
    for (int off = 1; off < 256; off <<= 1) {
        int v = (tid >= off) ? sc[tid - off] : 0;
        __syncthreads();
        sc[tid] += v;
        __syncthreads();
    }
    int off = g_bsum[blockIdx.x] + sc[tid] - s;
#pragma unroll
    for (int i = 0; i < 4; i++) {
        if (base + i < N_NODES) { g_rowptr[base + i] = off; g_cursor[base + i] = off; off += d[i]; }
    }
}

__global__ void k_fill(const int* __restrict__ ei) {
    int e = blockIdx.x * blockDim.x + threadIdx.x;
    if (e < N_EDGES) {
        int d = ei[N_EDGES + e];
        int p = atomicAdd(&g_cursor[d], 1);
        g_col[p] = ei[e];   // src
    }
}

// ---------------- layer-0 aggregation fused with embedding ---------------
__global__ void __launch_bounds__(256) k_aggr0(const int* __restrict__ x_idx,
                                               const float* __restrict__ emb,
                                               const float* __restrict__ epsArr,
                                               float* __restrict__ Hout) {
    int warp = (blockIdx.x * blockDim.x + threadIdx.x) >> 5;
    if (warp >= N_NODES) return;
    int lane = threadIdx.x & 31, c0 = lane * 2;
    float ev = 1.f + epsArr[0];
    int self = __ldg(&x_idx[warp]);
    float2 xv = *(const float2*)(emb + (size_t)self * HID + c0);
    float s0 = ev * xv.x, s1 = ev * xv.y;
    int start = g_rowptr[warp], deg = g_deg[warp];
    int j = 0;
    for (; j + 1 < deg; j += 2) {
        int n0 = __ldg(&x_idx[g_col[start + j]]);
        int n1 = __ldg(&x_idx[g_col[start + j + 1]]);
        float2 p = *(const float2*)(emb + (size_t)n0 * HID + c0);
        float2 q = *(const float2*)(emb + (size_t)n1 * HID + c0);
        s0 += p.x + q.x; s1 += p.y + q.y;
    }
    if (j < deg) {
        int n0 = __ldg(&x_idx[g_col[start + j]]);
        float2 p = *(const float2*)(emb + (size_t)n0 * HID + c0);
        s0 += p.x; s1 += p.y;
    }
    *(float2*)(Hout + (size_t)warp * HID + c0) = make_float2(s0, s1);
}

// ---------------- aggregation l>=1: f = relu(BN affine), BN from stats ----
__global__ void __launch_bounds__(256) k_aggr(const float* __restrict__ X,
                                              float* __restrict__ Hout,
                                              const float* __restrict__ epsArr,
                                              const float* __restrict__ statsIn,
                                              const float* __restrict__ gam,
                                              const float* __restrict__ bet,
                                              int layer) {
    __shared__ float sa[HID], sb[HID];
    int tid = threadIdx.x;
    if (tid < HID) {
        float s = statsIn[tid], q = statsIn[HID + tid];
        float m = s * INVN;
        float var = q * INVN - m * m;
        float a = gam[tid] * rsqrtf(var + 1e-5f);
        sa[tid] = a;
        sb[tid] = fmaf(-m, a, bet[tid]);
    }
    __syncthreads();
    int warp = (blockIdx.x * blockDim.x + tid) >> 5;
    if (warp >= N_NODES) return;
    int lane = tid & 31, c0 = lane * 2;
    float a0 = sa[c0], a1 = sa[c0 + 1], b0 = sb[c0], b1 = sb[c0 + 1];
    float ev = 1.f + epsArr[layer];

    float2 xv = *(const float2*)(X + (size_t)warp * HID + c0);
    float s0 = ev * fmaxf(fmaf(a0, xv.x, b0), 0.f);
    float s1 = ev * fmaxf(fmaf(a1, xv.y, b1), 0.f);

    int start = g_rowptr[warp], deg = g_deg[warp];
    int j = 0;
    for (; j + 1 < deg; j += 2) {
        int n0 = g_col[start + j], n1 = g_col[start + j + 1];
        float2 p = *(const float2*)(X + (size_t)n0 * HID + c0);
        float2 q = *(const float2*)(X + (size_t)n1 * HID + c0);
        s0 += fmaxf(fmaf(a0, p.x, b0), 0.f) + fmaxf(fmaf(a0, q.x, b0), 0.f);
        s1 += fmaxf(fmaf(a1, p.y, b1), 0.f) + fmaxf(fmaf(a1, q.y, b1), 0.f);
    }
    if (j < deg) {
        int n0 = g_col[start + j];
        float2 p = *(const float2*)(X + (size_t)n0 * HID + c0);
        s0 += fmaxf(fmaf(a0, p.x, b0), 0.f);
        s1 += fmaxf(fmaf(a1, p.y, b1), 0.f);
    }
    *(float2*)(Hout + (size_t)warp * HID + c0) = make_float2(s0, s1);
}

// ---------------- GEMM1: Y1 = H @ W1[l], FFMA2, + column stats ------------
#define G1_SMEM_FLOATS (128*64 + 64*128 + 2*128)
__global__ void __launch_bounds__(256, 2) k_gemm1(const float* __restrict__ A,
                                                  const float* __restrict__ W,
                                                  float* __restrict__ Y,
                                                  float* __restrict__ statsOut) {
    extern __shared__ float sm[];
    float* sA = sm;                 // [128][64]
    float* sW = sm + 128 * 64;      // [64][128] k-major
    float* sS = sW + 64 * 128;      // [256]
    int t = threadIdx.x;
    int row0 = blockIdx.x * 128;

    {   // W tile
        const float4* W4 = (const float4*)W;
        float4* sW4 = (float4*)sW;
#pragma unroll
        for (int i = 0; i < 8; i++) sW4[t + i * 256] = W4[t + i * 256];
    }
    {   // A tile
        int r = t >> 1, kh = (t & 1) * 32;
        int gr = row0 + r;
        float4* dst = (float4*)(sA + r * 64 + kh);
        if (gr < N_NODES) {
            const float4* src = (const float4*)(A + (size_t)gr * 64 + kh);
#pragma unroll
            for (int i = 0; i < 8; i++) dst[i] = src[i];
        } else {
#pragma unroll
            for (int i = 0; i < 8; i++) dst[i] = make_float4(0.f, 0.f, 0.f, 0.f);
        }
    }
    sS[t] = 0.f;
    __syncthreads();

    int tx = t & 15, ty = t >> 4;
    const float* aBase = sA + ty * 8 * 64;
    const float4* w4 = (const float4*)sW;

    unsigned long long acc[8][4];
#pragma unroll
    for (int i = 0; i < 8; i++)
#pragma unroll
        for (int j = 0; j < 4; j++) acc[i][j] = pk2(0.f, 0.f);

#pragma unroll 8
    for (int k = 0; k < 64; k++) {
        float4 wa = w4[k * 32 + tx];
        float4 wb = w4[k * 32 + 16 + tx];
        unsigned long long w01 = pk2(wa.x, wa.y), w23 = pk2(wa.z, wa.w);
        unsigned long long w45 = pk2(wb.x, wb.y), w67 = pk2(wb.z, wb.w);
#pragma unroll
        for (int i = 0; i < 8; i++) {
            float a = aBase[i * 64 + k];
            unsigned long long a2 = pk2(a, a);
            fma2(acc[i][0], a2, w01);
            fma2(acc[i][1], a2, w23);
            fma2(acc[i][2], a2, w45);
            fma2(acc[i][3], a2, w67);
        }
    }

    float cs[8], cq[8];
#pragma unroll
    for (int j = 0; j < 8; j++) { cs[j] = 0.f; cq[j] = 0.f; }
#pragma unroll
    for (int i = 0; i < 8; i++) {
        float2 p0 = up2(acc[i][0]), p1 = up2(acc[i][1]);
        float2 p2 = up2(acc[i][2]), p3 = up2(acc[i][3]);
        int gr = row0 + ty * 8 + i;
        if (gr < N_NODES) {
            *(float4*)(Y + (size_t)gr * 128 + tx * 4) = make_float4(p0.x, p0.y, p1.x, p1.y);
            *(float4*)(Y + (size_t)gr * 128 + 64 + tx * 4) = make_float4(p2.x, p2.y, p3.x, p3.y);
        }
        cs[0] += p0.x; cq[0] += p0.x * p0.x;
        cs[1] += p0.y; cq[1] += p0.y * p0.y;
        cs[2] += p1.x; cq[2] += p1.x * p1.x;
        cs[3] += p1.y; cq[3] += p1.y * p1.y;
        cs[4] += p2.x; cq[4] += p2.x * p2.x;
        cs[5] += p2.y; cq[5] += p2.y * p2.y;
        cs[6] += p3.x; cq[6] += p3.x * p3.x;
        cs[7] += p3.y; cq[7] += p3.y * p3.y;
    }
#pragma unroll
    for (int j = 0; j < 4; j++) {
        atomicAdd(&sS[tx * 4 + j], cs[j]);
        atomicAdd(&sS[128 + tx * 4 + j], cq[j]);
        atomicAdd(&sS[64 + tx * 4 + j], cs[4 + j]);
        atomicAdd(&sS[128 + 64 + tx * 4 + j], cq[4 + j]);
    }
    __syncthreads();
    atomicAdd(&statsOut[t], sS[t]);
}

// ---------------- GEMM2: X' = relu(BN(Y1)) @ W2[l], FFMA2, + stats --------
#define G2_SMEM_FLOATS (128*128 + 128*64 + 128 + 2*128)
__global__ void __launch_bounds__(256, 2) k_gemm2(const float* __restrict__ Yin,
                                                  const float* __restrict__ W,
                                                  float* __restrict__ Xout,
                                                  const float* __restrict__ statsIn,
                                                  const float* __restrict__ gam,
                                                  const float* __restrict__ bet,
                                                  float* __restrict__ statsOut) {
    extern __shared__ float sm[];
    float* sA  = sm;                   // [128][128]
    float* sW  = sm + 128 * 128;       // [128][64]
    float* sS  = sW + 128 * 64;        // [128]
    float* sTa = sS + 128;             // [128]
    float* sTb = sTa + 128;            // [128]
    int t = threadIdx.x;
    int row0 = blockIdx.x * 128;

    if (t < 128) {
        float s = statsIn[t], q = statsIn[128 + t];
        float m = s * INVN;
        float var = q * INVN - m * m;
        float a = gam[t] * rsqrtf(var + 1e-5f);
        sTa[t] = a;
        sTb[t] = fmaf(-m, a, bet[t]);
        sS[t] = 0.f;
    }
    __syncthreads();

    {   // W tile
        const float4* W4 = (const float4*)W;
        float4* sW4 = (float4*)sW;
#pragma unroll
        for (int i = 0; i < 8; i++) sW4[t + i * 256] = W4[t + i * 256];
    }
    {   // A tile with BN+relu transform
        int r = t >> 1, kh = (t & 1) * 64;
        int gr = row0 + r;
        float4* dst = (float4*)(sA + r * 128 + kh);
        if (gr < N_NODES) {
            const float4* src = (const float4*)(Yin + (size_t)gr * 128 + kh);
#pragma unroll
            for (int i = 0; i < 16; i++) {
                float4 y = src[i];
                float4 ta = *(const float4*)(sTa + kh + i * 4);
                float4 tb = *(const float4*)(sTb + kh + i * 4);
                float4 v;
                v.x = fmaxf(fmaf(ta.x, y.x, tb.x), 0.f);
                v.y = fmaxf(fmaf(ta.y, y.y, tb.y), 0.f);
                v.z = fmaxf(fmaf(ta.z, y.z, tb.z), 0.f);
                v.w = fmaxf(fmaf(ta.w, y.w, tb.w), 0.f);
                dst[i] = v;
            }
        } else {
#pragma unroll
            for (int i = 0; i < 16; i++) dst[i] = make_float4(0.f, 0.f, 0.f, 0.f);
        }
    }
    __syncthreads();

    int tx = t & 15, ty = t >> 4;
    const float* aBase = sA + ty * 8 * 128;
    const float4* w4 = (const float4*)sW;

    unsigned long long acc[8][2];
#pragma unroll
    for (int i = 0; i < 8; i++) { acc[i][0] = pk2(0.f, 0.f); acc[i][1] = pk2(0.f, 0.f); }

#pragma unroll 8
    for (int k = 0; k < 128; k++) {
        float4 w = w4[k * 16 + tx];
        unsigned long long w01 = pk2(w.x, w.y), w23 = pk2(w.z, w.w);
#pragma unroll
        for (int i = 0; i < 8; i++) {
            float a = aBase[i * 128 + k];
            unsigned long long a2 = pk2(a, a);
            fma2(acc[i][0], a2, w01);
            fma2(acc[i][1], a2, w23);
        }
    }

    float cs[4] = {0.f, 0.f, 0.f, 0.f}, cq[4] = {0.f, 0.f, 0.f, 0.f};
#pragma unroll
    for (int i = 0; i < 8; i++) {
        float2 p0 = up2(acc[i][0]), p1 = up2(acc[i][1]);
        int gr = row0 + ty * 8 + i;
        if (gr < N_NODES)
            *(float4*)(Xout + (size_t)gr * 64 + tx * 4) = make_float4(p0.x, p0.y, p1.x, p1.y);
        cs[0] += p0.x; cq[0] += p0.x * p0.x;
        cs[1] += p0.y; cq[1] += p0.y * p0.y;
        cs[2] += p1.x; cq[2] += p1.x * p1.x;
        cs[3] += p1.y; cq[3] += p1.y * p1.y;
    }
#pragma unroll
    for (int j = 0; j < 4; j++) {
        atomicAdd(&sS[tx * 4 + j], cs[j]);
        atomicAdd(&sS[64 + tx * 4 + j], cq[j]);
    }
    __syncthreads();
    if (t < 128) atomicAdd(&statsOut[t], sS[t]);
}

// ---------------- global mean pool per graph (batch is sorted) ------------
__global__ void k_pool(const float* __restrict__ X, const int* __restrict__ batch,
                       const float* __restrict__ statsIn,
                       const float* __restrict__ gam, const float* __restrict__ bet) {
    __shared__ float sa[HID], sb[HID];
    __shared__ float sred[4][HID];
    __shared__ int s_lo, s_hi;
    int tid = threadIdx.x, g = blockIdx.x;
    if (tid < HID) {
        float s = statsIn[tid], q = statsIn[HID + tid];
        float m = s * INVN;
        float var = q * INVN - m * m;
        float a = gam[tid] * rsqrtf(var + 1e-5f);
        sa[tid] = a;
        sb[tid] = fmaf(-m, a, bet[tid]);
    }
    if (tid == 0) {
        int lo = 0, hi = N_NODES;
        while (lo < hi) { int mid = (lo + hi) >> 1; if (batch[mid] < g) lo = mid + 1; else hi = mid; }
        s_lo = lo;
        lo = 0; hi = N_NODES; int gg = g + 1;
        while (lo < hi) { int mid = (lo + hi) >> 1; if (batch[mid] < gg) lo = mid + 1; else hi = mid; }
        s_hi = lo;
    }
    __syncthreads();
    int c = tid & 63, rg = tid >> 6;
    float acc = 0.f;
    for (int r = s_lo + rg; r < s_hi; r += 4) {
        float v = fmaf(sa[c], X[(size_t)r * HID + c], sb[c]);
        acc += fmaxf(v, 0.f);
    }
    sred[rg][c] = acc; __syncthreads();
    if (tid < HID) {
        float s = sred[0][c] + sred[1][c] + sred[2][c] + sred[3][c];
        int cnt = s_hi - s_lo;
        g_reps[g * HID + c] = s / (float)(cnt > 0 ? cnt : 1);
    }
}

// ---------------- finalize BN (head only): stats -> (a,b); rezero ---------
__global__ void k_fin(float* __restrict__ stats, const float* __restrict__ g,
                      const float* __restrict__ b, float* __restrict__ tf,
                      int width, float invN) {
    int t = threadIdx.x;
    if (t < width) {
        float s = stats[t], q = stats[width + t];
        float m = s * invN;
        float var = q * invN - m * m;
        float rstd = rsqrtf(var + 1e-5f);
        float a = g[t] * rstd;
        tf[t] = a;
        tf[width + t] = b[t] - m * a;
        stats[t] = 0.f; stats[width + t] = 0.f;
    }
}

// ---------------- tiny final-MLP GEMMs (M = 128 graphs) -------------------
__global__ void kf_gemm(const float* __restrict__ A, const float* __restrict__ W,
                        float* __restrict__ out, float* __restrict__ stats,
                        const float* __restrict__ tf, int K, int N) {
    int r = blockIdx.x, n = threadIdx.x;
    float acc = 0.f;
    for (int k = 0; k < K; k++) {
        float av = A[r * K + k];
        if (tf) av = fmaxf(fmaf(tf[k], av, tf[K + k]), 0.f);
        acc = fmaf(av, W[k * N + n], acc);
    }
    out[r * N + n] = acc;
    atomicAdd(&stats[n], acc);
    atomicAdd(&stats[N + n], acc * acc);
}

__global__ void kf_out(const float* __restrict__ T2v, const float* __restrict__ Wlin,
                       const float* __restrict__ blin, float* __restrict__ out) {
    int r = blockIdx.x, o = threadIdx.x;
    if (o < OUTD) {
        float acc = blin[o];
        for (int k = 0; k < DENSE; k++) {
            float av = fmaxf(fmaf(g_tfF[k], T2v[r * DENSE + k], g_tfF[DENSE + k]), 0.f);
            acc = fmaf(av, Wlin[k * OUTD + o], acc);
        }
        out[r * OUTD + o] = acc;
    }
}

// ---------------- launcher ------------------------------------------------
extern "C" void kernel_launch(void* const* d_in, const int* in_sizes, int n_in,
                              void* d_out, int out_size) {
    (void)in_sizes; (void)n_in; (void)out_size;
    const int*   x_idx = (const int*)d_in[0];
    const int*   ei    = (const int*)d_in[1];
    const int*   batch = (const int*)d_in[2];
    const float* emb   = (const float*)d_in[3];
    const float* eps   = (const float*)d_in[4];
    const float* W1    = (const float*)d_in[5];
    const float* g1    = (const float*)d_in[6];
    const float* b1    = (const float*)d_in[7];
    const float* W2    = (const float*)d_in[8];
    const float* g2    = (const float*)d_in[9];
    const float* b2    = (const float*)d_in[10];
    const float* Wf1   = (const float*)d_in[11];
    const float* gf1   = (const float*)d_in[12];
    const float* bf1   = (const float*)d_in[13];
    const float* Wf2   = (const float*)d_in[14];
    const float* gf2   = (const float*)d_in[15];
    const float* bf2   = (const float*)d_in[16];
    const float* Wlin  = (const float*)d_in[17];
    const float* blin  = (const float*)d_in[18];
    float* out = (float*)d_out;

    float *Xa, *Xb, *H, *Y1, *s128, *s64, *sF, *reps, *T1, *T2, *tfF;
    cudaGetSymbolAddress((void**)&Xa,   g_Xa);
    cudaGetSymbolAddress((void**)&Xb,   g_Xb);
    cudaGetSymbolAddress((void**)&H,    g_H);
    cudaGetSymbolAddress((void**)&Y1,   g_Y1);
    cudaGetSymbolAddress((void**)&s128, g_stats128);
    cudaGetSymbolAddress((void**)&s64,  g_stats64);
    cudaGetSymbolAddress((void**)&sF,   g_statsF);
    cudaGetSymbolAddress((void**)&reps, g_reps);
    cudaGetSymbolAddress((void**)&T1,   g_T1);
    cudaGetSymbolAddress((void**)&T2,   g_T2);
    cudaGetSymbolAddress((void**)&tfF,  g_tfF);

    static const size_t G1_BYTES = G1_SMEM_FLOATS * sizeof(float);
    static const size_t G2_BYTES = G2_SMEM_FLOATS * sizeof(float);
    cudaFuncSetAttribute(k_gemm1, cudaFuncAttributeMaxDynamicSharedMemorySize, (int)G1_BYTES);
    cudaFuncSetAttribute(k_gemm2, cudaFuncAttributeMaxDynamicSharedMemorySize, (int)G2_BYTES);

    k_setup<<<(N_NODES + 255) / 256, 256>>>();
    k_hist <<<(N_EDGES + 255) / 256, 256>>>(ei);
    k_scan1<<<SCAN_NB, 256>>>();
    k_scan2<<<1, 128>>>(SCAN_NB);
    k_scan3<<<SCAN_NB, 256>>>();
    k_fill <<<(N_EDGES + 255) / 256, 256>>>(ei);

    const int GEMM_GRID = (N_NODES + 127) / 128;   // 782
    float* Xcur = Xa; float* Xnext = Xb;
    for (int l = 0; l < 4; l++) {
        if (l == 0)
            k_aggr0<<<(N_NODES * 32 + 255) / 256, 256>>>(x_idx, emb, eps, H);
        else
            k_aggr<<<(N_NODES * 32 + 255) / 256, 256>>>(
                Xcur, H, eps, s64 + (l - 1) * 2 * HID,
                g2 + (l - 1) * HID, b2 + (l - 1) * HID, l);
        k_gemm1<<<GEMM_GRID, 256, G1_BYTES>>>(H, W1 + (size_t)l * HID * DENSE, Y1,
                                              s128 + l * 2 * DENSE);
        k_gemm2<<<GEMM_GRID, 256, G2_BYTES>>>(Y1, W2 + (size_t)l * DENSE * HID, Xnext,
                                              s128 + l * 2 * DENSE,
                                              g1 + l * DENSE, b1 + l * DENSE,
                                              s64 + l * 2 * HID);
        float* t = Xcur; Xcur = Xnext; Xnext = t;
    }
    k_pool<<<N_GRAPHS, 256>>>(Xcur, batch, s64 + 3 * 2 * HID, g2 + 3 * HID, b2 + 3 * HID);

    const float invG = 1.f / (float)N_GRAPHS;
    kf_gemm<<<N_GRAPHS, DENSE>>>(reps, Wf1, T1, sF, (const float*)0, HID, DENSE);
    k_fin<<<1, DENSE>>>(sF, gf1, bf1, tfF, DENSE, invG);
    kf_gemm<<<N_GRAPHS, DENSE>>>(T1, Wf2, T2, sF, tfF, DENSE, DENSE);
    k_fin<<<1, DENSE>>>(sF, gf2, bf2, tfF, DENSE, invG);
    kf_out<<<N_GRAPHS, 32>>>(T2, Wlin, blin, out);
}